// round 17
// baseline (speedup 1.0000x reference)
#include <cuda_runtime.h>
#include <cuda_fp16.h>
#include <cstdint>

#define D 128
#define MAXN 100000
#define MAXN_AL 100032               // padded to TM multiple
#define MAXE 1600000
#define PADK 136                     // padded fp16 row stride
#define ROW_U32 (PADK / 2)           // 68 u32 per fp16 row
#define W_IMG_U32 (128 * PADK / 2)   // 8704 u32 for W image
#define TM 64                        // GEMM CTA row tile
#define HS_BLOCKS 148                // co-resident grid for hist+scan
#define SCAN_CHUNKS 98               // ceil(100000/1024)

// ---------------- scratch (static device mem) ------------------------------
__device__ unsigned g_W16[W_IMG_U32];           // W as fp16, [n][PADK]
__device__ unsigned g_h16[MAXN * 64];           // h as fp16, [node][128]
__device__ unsigned g_A16[MAXN_AL * ROW_U32];   // gathered A as fp16 (zero-init)
__device__ int g_cnt[MAXN];
__device__ int g_off[MAXN + 1];
__device__ int g_csr[MAXE];
__device__ int g_blk[256];
__device__ unsigned g_bar;                      // grid-barrier counter

// ---------------------------------------------------------------------------
// init (fused): W -> fp16 image | zero g_cnt + g_bar | h -> fp16 image
// ---------------------------------------------------------------------------
__global__ void k_init(const float* __restrict__ W, const float* __restrict__ h,
                       int n, int zeroBlocks) {
    int b = blockIdx.x, t = threadIdx.x;
    if (b < 32) {                            // W prep
        int row = b * 4 + (t >> 6);
        int k = (t & 63) * 2;
        half2 p = __float22half2_rn(make_float2(W[row * D + k], W[row * D + k + 1]));
        g_W16[(unsigned)(row * PADK + k) / 2] = *(unsigned*)&p;
        if (b == 0 && t == 0) g_bar = 0;
    } else if (b < 32 + zeroBlocks) {        // zero g_cnt
        int i = (b - 32) * 256 + t;
        if (i < n) g_cnt[i] = 0;
    } else {                                 // h -> fp16 (one float4 per thread)
        int i = (b - 32 - zeroBlocks) * 256 + t;
        int n4 = n * 32;
        if (i < n4) {
            float4 v = __ldg((const float4*)h + i);
            half2 p0 = __float22half2_rn(make_float2(v.x, v.y));
            half2 p1 = __float22half2_rn(make_float2(v.z, v.w));
            uint2 o;
            o.x = *(unsigned*)&p0;
            o.y = *(unsigned*)&p1;
            *((uint2*)g_h16 + i) = o;
        }
    }
}

// ---------------------------------------------------------------------------
// grid barrier (all HS_BLOCKS co-resident by construction)
// ---------------------------------------------------------------------------
__device__ __forceinline__ void grid_bar(unsigned target) {
    __syncthreads();
    if (threadIdx.x == 0) {
        __threadfence();
        atomicAdd(&g_bar, 1u);
        while (atomicAdd(&g_bar, 0u) < target) { }
    }
    __syncthreads();
}

// ---------------------------------------------------------------------------
// hist + 3-phase scan fused into one co-resident kernel.
// phase 1: histogram (grid-stride REDG).  barrier.
// phase 2: block b<98 computes local scan of its 1024-chunk + total -> g_blk.
// barrier.  phase 3: block sums predecessors' totals, writes g_off/g_cnt.
// ---------------------------------------------------------------------------
__global__ void __launch_bounds__(256, 1)
k_histscan(const int* __restrict__ dst, int E, int n) {
    int b = blockIdx.x, t = threadIdx.x;

    // ---- phase 1: histogram ----
    {
        int i = b * 256 + t;
        int stride = HS_BLOCKS * 256;
#pragma unroll 4
        for (; i < E; i += stride) atomicAdd(&g_cnt[dst[i]], 1);
    }
    grid_bar(HS_BLOCKS);

    // ---- phase 2: local chunk scan ----
    __shared__ int wsum[8];
    int v0 = 0, v1 = 0, v2 = 0, v3 = 0, excl = 0;
    if (b < SCAN_CHUNKS) {
        int base = b * 1024 + t * 4;
        v0 = (base + 0 < n) ? g_cnt[base + 0] : 0;
        v1 = (base + 1 < n) ? g_cnt[base + 1] : 0;
        v2 = (base + 2 < n) ? g_cnt[base + 2] : 0;
        v3 = (base + 3 < n) ? g_cnt[base + 3] : 0;
        int s = v0 + v1 + v2 + v3;

        int lane = t & 31, w = t >> 5;
        int inc = s;
#pragma unroll
        for (int o = 1; o < 32; o <<= 1) {
            int x = __shfl_up_sync(0xffffffffu, inc, o);
            if (lane >= o) inc += x;
        }
        if (lane == 31) wsum[w] = inc;
        __syncthreads();
        if (t == 0) {
            int run = 0;
#pragma unroll
            for (int i = 0; i < 8; i++) { int tmp = wsum[i]; wsum[i] = run; run += tmp; }
            g_blk[b] = run;                 // chunk total
        }
        __syncthreads();
        excl = wsum[w] + inc - s;           // local exclusive prefix
    }
    grid_bar(2 * HS_BLOCKS);

    // ---- phase 3: add predecessor totals, write out ----
    if (b < SCAN_CHUNKS) {
        __shared__ int pre;
        // parallel sum of g_blk[0..b): threads t<b load, reduce in smem
        __shared__ int red[256];
        red[t] = (t < b) ? g_blk[t] : 0;
        __syncthreads();
#pragma unroll
        for (int o = 128; o > 0; o >>= 1) {
            if (t < o) red[t] += red[t + o];
            __syncthreads();
        }
        if (t == 0) pre = red[0];
        __syncthreads();

        int base = b * 1024 + t * 4;
        int e0 = pre + excl;
        if (base + 0 < n) { g_off[base + 0] = e0;            g_cnt[base + 0] = e0; }
        if (base + 1 < n) { g_off[base + 1] = e0 + v0;       g_cnt[base + 1] = e0 + v0; }
        if (base + 2 < n) { g_off[base + 2] = e0 + v0 + v1;  g_cnt[base + 2] = e0 + v0 + v1; }
        if (base + 3 < n) { g_off[base + 3] = e0 + v0 + v1 + v2;
                            g_cnt[base + 3] = e0 + v0 + v1 + v2; }
        if (b == 0 && t == 0) g_off[n] = E;
    }
}

// ---------------------------------------------------------------------------
// fill (proven scalar grid-stride)
// ---------------------------------------------------------------------------
__global__ void k_fill(const int* __restrict__ src, const int* __restrict__ dst, int E) {
    int i = blockIdx.x * blockDim.x + threadIdx.x;
    int stride = gridDim.x * blockDim.x;
    for (; i < E; i += stride) {
        int pos = atomicAdd(&g_cnt[dst[i]], 1);
        g_csr[pos] = src[i];
    }
}

// ---------------------------------------------------------------------------
// Gather from fp16 image -> fp16 A image (fp32 accumulation), proven R16.
// ---------------------------------------------------------------------------
__global__ void k_gather(int N) {
    int node = blockIdx.x * 8 + (threadIdx.x >> 5);
    if (node >= N) return;
    int lane = threadIdx.x & 31;

    int beg = g_off[node];
    int end = g_off[node + 1];

    const uint2* hp = (const uint2*)g_h16;

    float4 a0 = make_float4(0.f, 0.f, 0.f, 0.f);
    float4 a1 = make_float4(0.f, 0.f, 0.f, 0.f);
    float4 a2 = make_float4(0.f, 0.f, 0.f, 0.f);
    float4 a3 = make_float4(0.f, 0.f, 0.f, 0.f);

    int e = beg;
    for (; e + 3 < end; e += 4) {
        int s0 = __ldg(&g_csr[e]);
        int s1 = __ldg(&g_csr[e + 1]);
        int s2 = __ldg(&g_csr[e + 2]);
        int s3 = __ldg(&g_csr[e + 3]);
        uint2 v0 = __ldg(&hp[(size_t)s0 * 32 + lane]);
        uint2 v1 = __ldg(&hp[(size_t)s1 * 32 + lane]);
        uint2 v2 = __ldg(&hp[(size_t)s2 * 32 + lane]);
        uint2 v3 = __ldg(&hp[(size_t)s3 * 32 + lane]);
        float2 f;
        f = __half22float2(*(half2*)&v0.x); a0.x += f.x; a0.y += f.y;
        f = __half22float2(*(half2*)&v0.y); a0.z += f.x; a0.w += f.y;
        f = __half22float2(*(half2*)&v1.x); a1.x += f.x; a1.y += f.y;
        f = __half22float2(*(half2*)&v1.y); a1.z += f.x; a1.w += f.y;
        f = __half22float2(*(half2*)&v2.x); a2.x += f.x; a2.y += f.y;
        f = __half22float2(*(half2*)&v2.y); a2.z += f.x; a2.w += f.y;
        f = __half22float2(*(half2*)&v3.x); a3.x += f.x; a3.y += f.y;
        f = __half22float2(*(half2*)&v3.y); a3.z += f.x; a3.w += f.y;
    }
    for (; e < end; e++) {
        int s0 = __ldg(&g_csr[e]);
        uint2 v0 = __ldg(&hp[(size_t)s0 * 32 + lane]);
        float2 f;
        f = __half22float2(*(half2*)&v0.x); a0.x += f.x; a0.y += f.y;
        f = __half22float2(*(half2*)&v0.y); a0.z += f.x; a0.w += f.y;
    }
    float4 s4;
    s4.x = (a0.x + a1.x) + (a2.x + a3.x);
    s4.y = (a0.y + a1.y) + (a2.y + a3.y);
    s4.z = (a0.z + a1.z) + (a2.z + a3.z);
    s4.w = (a0.w + a1.w) + (a2.w + a3.w);

    half2 p0 = __float22half2_rn(make_float2(s4.x, s4.y));
    half2 p1 = __float22half2_rn(make_float2(s4.z, s4.w));
    unsigned idx = (unsigned)node * ROW_U32 + lane * 2;
    *(uint2*)&g_A16[idx] = make_uint2(*(unsigned*)&p0, *(unsigned*)&p1);
}

// ---------------------------------------------------------------------------
// Tensor-core GEMM (proven R16): single-pass fp16, 64-row tile, 3 CTAs/SM.
// ---------------------------------------------------------------------------
#define SM_W 0
#define SM_A (SM_W + 128 * PADK * 2)          // 34816
#define SM_BIAS (SM_A + TM * PADK * 2)        // 52224
#define SM_TOTAL (SM_BIAS + 512)              // 52736

__device__ __forceinline__ void mma_fp16(float& c0, float& c1, float& c2, float& c3,
                                         unsigned a0, unsigned a1, unsigned a2, unsigned a3,
                                         unsigned b0, unsigned b1) {
    asm volatile(
        "mma.sync.aligned.m16n8k16.row.col.f32.f16.f16.f32 "
        "{%0,%1,%2,%3}, {%4,%5,%6,%7}, {%8,%9}, {%0,%1,%2,%3};"
        : "+f"(c0), "+f"(c1), "+f"(c2), "+f"(c3)
        : "r"(a0), "r"(a1), "r"(a2), "r"(a3), "r"(b0), "r"(b1));
}

__global__ void __launch_bounds__(256, 3)
k_gemm_mma(const float* __restrict__ bias,
           float* __restrict__ out, int M) {
    extern __shared__ char sm[];
    int tid = threadIdx.x;
    int wid = tid >> 5;
    int lane = tid & 31;
    int m0 = blockIdx.x * TM;

    if (tid < 128) *(float*)(sm + SM_BIAS + tid * 4) = bias[tid];

    {
        const uint4* sw = (const uint4*)g_W16;
        uint4* dw = (uint4*)(sm + SM_W);
        for (int i = tid; i < W_IMG_U32 / 4; i += 256) dw[i] = sw[i];
    }
    {
        const uint4* sa = (const uint4*)g_A16 + (size_t)m0 * (ROW_U32 / 4);
        uint4* da = (uint4*)(sm + SM_A);
#pragma unroll
        for (int j = 0; j < 5; j++) {
            int i = j * 256 + tid;
            if (i < TM * (ROW_U32 / 4)) da[i] = sa[i];
        }
    }
    __syncthreads();

    int wm = (wid & 3) * 16;
    int wn = (wid >> 2) * 64;
    int g = lane >> 2;
    int t = lane & 3;

    float acc[8][4];
#pragma unroll
    for (int nt = 0; nt < 8; nt++)
#pragma unroll
        for (int i = 0; i < 4; i++) acc[nt][i] = 0.f;

    const char* As = sm + SM_A;
    const char* Ws = sm + SM_W;
#pragma unroll
    for (int ks = 0; ks < 8; ks++) {
        int k0 = ks * 16;
        unsigned a[4];
        {
            unsigned base = (unsigned)((wm + g) * PADK + k0 + 2 * t) * 2;
            a[0] = *(const unsigned*)(As + base);
            a[1] = *(const unsigned*)(As + base + 8 * PADK * 2);
            a[2] = *(const unsigned*)(As + base + 16);
            a[3] = *(const unsigned*)(As + base + 8 * PADK * 2 + 16);
        }
        unsigned bb[8][2];
#pragma unroll
        for (int nt = 0; nt < 8; nt++) {
            unsigned base = (unsigned)((wn + nt * 8 + g) * PADK + k0 + 2 * t) * 2;
            bb[nt][0] = *(const unsigned*)(Ws + base);
            bb[nt][1] = *(const unsigned*)(Ws + base + 16);
        }
#pragma unroll
        for (int nt = 0; nt < 8; nt++)
            mma_fp16(acc[nt][0], acc[nt][1], acc[nt][2], acc[nt][3],
                     a[0], a[1], a[2], a[3], bb[nt][0], bb[nt][1]);
    }

    {
        const float* bs = (const float*)(sm + SM_BIAS);
        int r0 = wm + g;
        int gm0 = m0 + r0;
        int gm1 = gm0 + 8;
#pragma unroll
        for (int nt = 0; nt < 8; nt++) {
            int c = wn + nt * 8 + 2 * t;
            float2 bv = *(const float2*)(bs + c);
            if (gm0 < M) {
                float2 o;
                o.x = fmaxf(acc[nt][0] + bv.x, 0.f);
                o.y = fmaxf(acc[nt][1] + bv.y, 0.f);
                *(float2*)(out + (size_t)gm0 * D + c) = o;
            }
            if (gm1 < M) {
                float2 o;
                o.x = fmaxf(acc[nt][2] + bv.x, 0.f);
                o.y = fmaxf(acc[nt][3] + bv.y, 0.f);
                *(float2*)(out + (size_t)gm1 * D + c) = o;
            }
        }
    }
}

// ---------------------------------------------------------------------------
// Launch: 5 kernels
// ---------------------------------------------------------------------------
extern "C" void kernel_launch(void* const* d_in, const int* in_sizes, int n_in,
                              void* d_out, int out_size) {
    const float* h    = (const float*)d_in[0];
    const int*   esrc = (const int*)d_in[1];
    const int*   edst = (const int*)d_in[2];
    const float* W    = (const float*)d_in[3];
    const float* b    = (const float*)d_in[4];
    float* out = (float*)d_out;

    int M = in_sizes[0] / D;   // 100000
    int E = in_sizes[1];       // 1600000

    cudaFuncSetAttribute(k_gemm_mma, cudaFuncAttributeMaxDynamicSharedMemorySize,
                         SM_TOTAL);

    int zeroBlocks = (M + 255) / 256;          // 391
    int convBlocks = (M * 32 + 255) / 256;     // 12500

    k_init<<<32 + zeroBlocks + convBlocks, 256>>>(W, h, M, zeroBlocks);
    k_histscan<<<HS_BLOCKS, 256>>>(edst, E, M);
    k_fill<<<1024, 256>>>(esrc, edst, E);
    k_gather<<<(M + 7) / 8, 256>>>(M);
    k_gemm_mma<<<(M + TM - 1) / TM, 256, SM_TOTAL>>>(b, out, M);
}